// round 2
// baseline (speedup 1.0000x reference)
#include <cuda_runtime.h>
#include <math.h>

#define N_NODES 256
#define E_EDGES 320
#define DE      640      // 2E directed edges
#define HV      128
#define MV      128
#define DISD    8
#define ANGD    16
#define CAP     64       // max edges per vertex (Poisson(2.5); 64 is astronomically safe)
#define WATT_LD 416
#define WLNK_LD 264

// ---------------- scratch (device globals; no allocation) ----------------
__device__ int   g_U[DE], g_V[DE];
__device__ float g_norm[DE * 3];        // normalized q_uv
__device__ float g_disftr[DE * DISD];   // tanh(tanh(dis) W_dis)
__device__ float g_align[DE];           // per directed-edge alignment logit
__device__ float g_a[DE * MV];          // a_i
__device__ float g_b[DE * MV];          // b_j
__device__ float g_me2[DE * MV];        // link features pre-combine
__device__ float g_att[DE * MV];        // attend_ftr
__device__ int   g_adjU_cnt[N_NODES], g_adjV_cnt[N_NODES];
__device__ int   g_adjU[N_NODES * CAP], g_adjV[N_NODES * CAP];

__device__ __forceinline__ float dot4(float4 a, float4 b) {
    return a.x * b.x + a.y * b.y + a.z * b.z + a.w * b.w;
}

// ---------------- K1: decode one-hot incidence to index arrays ----------------
__global__ void k_decode(const float* __restrict__ vew1, const float* __restrict__ vew2) {
    int e = threadIdx.x;
    if (e >= E_EDGES) return;
    int u = 0, v = 0;
    for (int n = 0; n < N_NODES; n++) {
        if (vew1[n * E_EDGES + e] != 0.0f) u = n;   // columns are one-hot
        if (vew2[n * E_EDGES + e] != 0.0f) v = n;
    }
    g_U[e] = u;           g_V[e] = v;
    g_U[e + E_EDGES] = v; g_V[e + E_EDGES] = u;     // reversed copies
}

// ---------------- K2: deterministic adjacency lists (no atomics) ----------------
__global__ void k_adj() {
    int n = blockIdx.x * blockDim.x + threadIdx.x;
    if (n >= N_NODES) return;
    int cu = 0, cv = 0;
    for (int d = 0; d < DE; d++) {
        if (g_U[d] == n && cu < CAP) g_adjU[n * CAP + cu++] = d;
        if (g_V[d] == n && cv < CAP) g_adjV[n * CAP + cv++] = d;
    }
    g_adjU_cnt[n] = cu;
    g_adjV_cnt[n] = cv;
}

// ---------------- K3: per-edge scalar features + align logit ----------------
__global__ void k_feats(const float* __restrict__ q, const float* __restrict__ he,
                        const float* __restrict__ W_align, const float* __restrict__ b_align,
                        const float* __restrict__ W_dis, const float* __restrict__ b_dis) {
    int d = blockIdx.x;
    int t = threadIdx.x;
    __shared__ float red[128];
    red[t] = he[(d % E_EDGES) * HV + t] * W_align[t];
    __syncthreads();
    #pragma unroll
    for (int s = 64; s > 0; s >>= 1) {
        if (t < s) red[t] += red[t + s];
        __syncthreads();
    }
    if (t == 0) {
        g_align[d] = red[0] + b_align[0];
        int u = g_U[d], v = g_V[d];
        float qx = q[v * 3 + 0] - q[u * 3 + 0];
        float qy = q[v * 3 + 1] - q[u * 3 + 1];
        float qz = q[v * 3 + 2] - q[u * 3 + 2];
        float dis = sqrtf(qx * qx + qy * qy + qz * qz) + 1e-6f;
        float inv = 1.0f / dis;
        g_norm[d * 3 + 0] = qx * inv;
        g_norm[d * 3 + 1] = qy * inv;
        g_norm[d * 3 + 2] = qz * inv;
        float td = tanhf(dis);
        #pragma unroll
        for (int k = 0; k < DISD; k++)
            g_disftr[d * DISD + k] = tanhf(td * W_dis[k] + b_dis[k]);
    }
}

// ---------------- K4: fused 3-output GEMM (a_i, b_j, me2) ----------------
// Block = 8 directed edges x all 128 output cols. Each thread owns one output
// column m, streams its weight rows (float4) once, reuses across 8 edges.
__global__ void __launch_bounds__(128) k_gemm(const float* __restrict__ hv,
                                              const float* __restrict__ W_att,
                                              const float* __restrict__ W_link,
                                              const float* __restrict__ b_link) {
    int base = blockIdx.x * 8;
    int m = threadIdx.x;
    __shared__ float4 shv[8][HV / 4];   // hv[V[d]]
    __shared__ float4 shu[8][HV / 4];   // hv[U[d]]
    __shared__ float4 sdis[8][DISD / 4];

    #pragma unroll
    for (int dd = 0; dd < 8; dd++) {
        int d = base + dd;
        ((float*)shv[dd])[m] = hv[g_V[d] * HV + m];
        ((float*)shu[dd])[m] = hv[g_U[d] * HV + m];
        if (m < DISD) ((float*)sdis[dd])[m] = g_disftr[d * DISD + m];
    }
    __syncthreads();

    float acc_a[8], acc_b[8], acc_m[8];
    #pragma unroll
    for (int dd = 0; dd < 8; dd++) { acc_a[dd] = 0.f; acc_b[dd] = 0.f; acc_m[dd] = 0.f; }

    const float4* wrow = (const float4*)(W_att + m * WATT_LD);   // 416-wide row
    const float4* lrow = (const float4*)(W_link + m * WLNK_LD);  // 264-wide row

    // hv_v / hv_u blocks (128 cols each)
    for (int k = 0; k < HV / 4; k++) {
        float4 wva = wrow[k];        // A: hv_v -> cols [0,128)
        float4 wua = wrow[34 + k];   // A: hv_u -> cols [136,264)
        float4 wvb = wrow[66 + k];   // b: hv_v -> cols [264,392)
        float4 wum = lrow[k];        // link: hv_u -> cols [0,128)
        float4 wvm = lrow[34 + k];   // link: hv_v -> cols [136,264)
        #pragma unroll
        for (int dd = 0; dd < 8; dd++) {
            float4 hvv = shv[dd][k];
            float4 huu = shu[dd][k];
            acc_a[dd] += dot4(hvv, wva) + dot4(huu, wua);
            acc_b[dd] += dot4(hvv, wvb);
            acc_m[dd] += dot4(huu, wum) + dot4(hvv, wvm);
        }
    }
    // dis block (8 cols)
    #pragma unroll
    for (int k = 0; k < DISD / 4; k++) {
        float4 wda = wrow[32 + k];   // A: dis -> cols [128,136)
        float4 wdb = wrow[98 + k];   // b: dis -> cols [392,400)
        float4 wdm = lrow[32 + k];   // link: dis -> cols [128,136)
        #pragma unroll
        for (int dd = 0; dd < 8; dd++) {
            float4 ds = sdis[dd][k];
            acc_a[dd] += dot4(ds, wda);
            acc_b[dd] += dot4(ds, wdb);
            acc_m[dd] += dot4(ds, wdm);
        }
    }

    float bl = b_link[m];
    #pragma unroll
    for (int dd = 0; dd < 8; dd++) {
        int d = base + dd;
        g_a[d * MV + m]   = acc_a[dd];
        g_b[d * MV + m]   = acc_b[dd];
        g_me2[d * MV + m] = acc_m[dd] + bl;
    }
}

// ---------------- K5: sparse attend (max over relu'd neighbor scores) ----------------
__global__ void __launch_bounds__(128) k_attend(const float* __restrict__ W_att,
                                                const float* __restrict__ W_ang,
                                                const float* __restrict__ b_ang) {
    int i = blockIdx.x;
    int t = threadIdx.x;
    __shared__ float sh_t[ANGD];

    float wc[ANGD];
    #pragma unroll
    for (int k = 0; k < ANGD; k++) wc[k] = W_att[t * WATT_LD + 400 + k];

    float ai  = g_a[i * MV + t];
    float nix = g_norm[i * 3 + 0], niy = g_norm[i * 3 + 1], niz = g_norm[i * 3 + 2];
    int   u   = g_U[i];
    int   cnt = g_adjU_cnt[u];

    float amax = 0.0f;  // relu floor: ee=0 entries contribute exactly 0
    for (int idx = 0; idx < cnt; idx++) {
        int j = g_adjU[u * CAP + idx];
        if (t < ANGD) {
            float ang = nix * g_norm[j * 3 + 0] + niy * g_norm[j * 3 + 1] + niz * g_norm[j * 3 + 2];
            sh_t[t] = tanhf(ang * W_ang[t] + b_ang[t]);
        }
        __syncthreads();
        float c = 0.0f;
        #pragma unroll
        for (int k = 0; k < ANGD; k++) c += sh_t[k] * wc[k];
        float s = ai + g_b[j * MV + t] + c;
        amax = fmaxf(amax, s);
        __syncthreads();
    }
    g_att[i * MV + t] = amax;
}

// ---------------- K6: softmax-gather + elu -> mv_ftr ----------------
__global__ void __launch_bounds__(128) k_mv(float* __restrict__ out) {
    int n = blockIdx.x;
    int t = threadIdx.x;
    int cnt = g_adjV_cnt[n];
    float r;
    if (cnt == 0) {
        // all logits == -1e6 -> uniform softmax over all 640 edges
        float s = 0.0f;
        for (int d = 0; d < DE; d++) s += g_att[d * MV + t];
        r = s * (1.0f / (float)DE);
    } else {
        float mx = -1e30f;
        for (int idx = 0; idx < cnt; idx++)
            mx = fmaxf(mx, g_align[g_adjV[n * CAP + idx]]);
        float den = 0.0f, acc = 0.0f;
        for (int idx = 0; idx < cnt; idx++) {
            int d = g_adjV[n * CAP + idx];
            float w = expf(g_align[d] - mx);
            den += w;
            acc += w * g_att[d * MV + t];
        }
        r = acc / den;
    }
    out[n * MV + t] = (r > 0.0f) ? r : expm1f(r);  // elu
}

// ---------------- K7: me epilogue (leaky_relu of forward+reverse) ----------------
__global__ void __launch_bounds__(128) k_me(float* __restrict__ out) {
    int e = blockIdx.x;
    int t = threadIdx.x;
    float x = g_me2[e * MV + t] + g_me2[(e + E_EDGES) * MV + t];
    out[N_NODES * MV + e * MV + t] = (x >= 0.0f) ? x : 0.01f * x;
}

// ---------------- launch ----------------
extern "C" void kernel_launch(void* const* d_in, const int* in_sizes, int n_in,
                              void* d_out, int out_size) {
    const float* hv      = (const float*)d_in[0];
    const float* he      = (const float*)d_in[1];
    // d_in[2] = p_ftr (unused by reference)
    const float* q       = (const float*)d_in[3];
    const float* vew1    = (const float*)d_in[4];
    const float* vew2    = (const float*)d_in[5];
    // d_in[6], d_in[7] = veb1, veb2 (semantics reproduced via incidence)
    const float* W_dis   = (const float*)d_in[8];
    const float* b_dis   = (const float*)d_in[9];
    const float* W_ang   = (const float*)d_in[10];
    const float* b_ang   = (const float*)d_in[11];
    const float* W_att   = (const float*)d_in[12];
    const float* W_align = (const float*)d_in[13];
    const float* b_align = (const float*)d_in[14];
    const float* W_link  = (const float*)d_in[15];
    const float* b_link  = (const float*)d_in[16];
    float* out = (float*)d_out;

    k_decode<<<1, E_EDGES>>>(vew1, vew2);
    k_adj<<<2, 128>>>();
    k_feats<<<DE, 128>>>(q, he, W_align, b_align, W_dis, b_dis);
    k_gemm<<<DE / 8, 128>>>(hv, W_att, W_link, b_link);
    k_attend<<<DE, 128>>>(W_att, W_ang, b_ang);
    k_mv<<<N_NODES, 128>>>(out);
    k_me<<<E_EDGES, 128>>>(out);
}

// round 3
// speedup vs baseline: 3.3795x; 3.3795x over previous
#include <cuda_runtime.h>
#include <math.h>

#define N_NODES 256
#define E_EDGES 320
#define DE      640      // 2E directed edges
#define HV      128
#define MV      128
#define DISD    8
#define ANGD    16
#define CAP     64
#define WATT_LD 416
#define WLNK_LD 264

// ---------------- scratch (device globals; no allocation) ----------------
__device__ int   g_U[DE], g_V[DE];
__device__ float g_norm[DE * 3];
__device__ float g_align[DE];
__device__ float g_a[DE * MV];
__device__ float g_b[DE * MV];
__device__ float g_att[DE * MV];
__device__ float g_attsum[4 * MV];      // 4-way padded column sums of g_att
__device__ float g_wc[ANGD * MV];       // W_att[:,400:416] transposed [k][m]
__device__ int   g_adjU_cnt[N_NODES], g_adjV_cnt[N_NODES];
__device__ int   g_adjU[N_NODES * CAP], g_adjV[N_NODES * CAP];

__device__ __forceinline__ float dot4(float4 a, float4 b) {
    return a.x * b.x + a.y * b.y + a.z * b.z + a.w * b.w;
}

// ================= K1: decode + adjacency + transposes (one kernel) ==========
// blocks [0,320): decode one-hot incidence (coalesced, unique writer per cell)
// blocks [320,352): per-node adjacency via warp-ballot ordered append
// block  352: zero attsum + transpose W_att angle columns
__global__ void __launch_bounds__(256) k_build(const float* __restrict__ vew1,
                                               const float* __restrict__ vew2,
                                               const float* __restrict__ W_att) {
    int b = blockIdx.x;
    int t = threadIdx.x;
    if (b < 320) {
        int idx = b * 256 + t;                 // idx = n*E + e, coalesced
        int e = idx % E_EDGES, n = idx / E_EDGES;
        if (vew1[idx] != 0.0f) { g_U[e] = n; g_V[e + E_EDGES] = n; }
        if (vew2[idx] != 0.0f) { g_V[e] = n; g_U[e + E_EDGES] = n; }
    } else if (b < 352) {
        int w = t >> 5, lane = t & 31;
        int n = (b - 320) * 8 + w;             // one warp per node
        unsigned lml = (1u << lane) - 1u;
        int cu = 0, cv = 0;
        // pass 1: vew1 -> adjU (d=e), vew2 -> adjV (d=e)
        for (int e0 = 0; e0 < E_EDGES; e0 += 32) {
            int e = e0 + lane;
            float a = vew1[n * E_EDGES + e];
            float c = vew2[n * E_EDGES + e];
            unsigned m1 = __ballot_sync(0xFFFFFFFFu, a != 0.0f);
            unsigned m2 = __ballot_sync(0xFFFFFFFFu, c != 0.0f);
            if (a != 0.0f) g_adjU[n * CAP + cu + __popc(m1 & lml)] = e;
            if (c != 0.0f) g_adjV[n * CAP + cv + __popc(m2 & lml)] = e;
            cu += __popc(m1); cv += __popc(m2);
        }
        // pass 2: vew2 -> adjU (d=e+E), vew1 -> adjV (d=e+E)
        for (int e0 = 0; e0 < E_EDGES; e0 += 32) {
            int e = e0 + lane;
            float a = vew1[n * E_EDGES + e];
            float c = vew2[n * E_EDGES + e];
            unsigned m1 = __ballot_sync(0xFFFFFFFFu, c != 0.0f);
            unsigned m2 = __ballot_sync(0xFFFFFFFFu, a != 0.0f);
            if (c != 0.0f) g_adjU[n * CAP + cu + __popc(m1 & lml)] = e + E_EDGES;
            if (a != 0.0f) g_adjV[n * CAP + cv + __popc(m2 & lml)] = e + E_EDGES;
            cu += __popc(m1); cv += __popc(m2);
        }
        if (lane == 0) { g_adjU_cnt[n] = cu; g_adjV_cnt[n] = cv; }
    } else {
        for (int j = t; j < 4 * MV; j += 256) g_attsum[j] = 0.0f;
        for (int j = t; j < ANGD * MV; j += 256) {
            int k = j / MV, m = j % MV;
            g_wc[j] = W_att[m * WATT_LD + 400 + k];
        }
    }
}

// ========== K2: fused feats + 3-output GEMM + me epilogue =====================
// Block = 2 forward edges (e0, e0+1) + their reverses. 256 threads: m = t&127,
// h = t>>7 splits the K reduction in half. Reverse edges reuse swapped tiles.
__global__ void __launch_bounds__(256) k_gemm(const float* __restrict__ hv,
                                              const float* __restrict__ he,
                                              const float* __restrict__ q,
                                              const float* __restrict__ W_att,
                                              const float* __restrict__ W_link,
                                              const float* __restrict__ b_link,
                                              const float* __restrict__ W_align,
                                              const float* __restrict__ b_align,
                                              const float* __restrict__ W_dis,
                                              const float* __restrict__ b_dis,
                                              float* __restrict__ out) {
    int e0 = blockIdx.x * 2;
    int t = threadIdx.x;
    int m = t & 127;
    int h = t >> 7;

    __shared__ __align__(16) float su[2][HV], sv[2][HV];
    __shared__ __align__(16) float sdis[2][DISD];
    __shared__ float sred[256];
    __shared__ float spart[12][MV];     // half-1 partial accumulators

    int e = e0 + h;                     // each half owns one forward edge
    int u = g_U[e], v = g_V[e];
    su[h][m] = hv[u * HV + m];
    sv[h][m] = hv[v * HV + m];

    // align logit (reduce within each half)
    sred[t] = he[e * HV + m] * W_align[m];
    __syncthreads();
    #pragma unroll
    for (int s = 64; s > 0; s >>= 1) {
        if (m < s) sred[t] += sred[t + s];
        __syncthreads();
    }
    if (m == 0) {
        float al = sred[h * 128] + b_align[0];
        g_align[e] = al;
        g_align[e + E_EDGES] = al;
        float qx = q[v * 3 + 0] - q[u * 3 + 0];
        float qy = q[v * 3 + 1] - q[u * 3 + 1];
        float qz = q[v * 3 + 2] - q[u * 3 + 2];
        float dis = sqrtf(qx * qx + qy * qy + qz * qz) + 1e-6f;
        float inv = 1.0f / dis;
        g_norm[e * 3 + 0] = qx * inv;
        g_norm[e * 3 + 1] = qy * inv;
        g_norm[e * 3 + 2] = qz * inv;
        g_norm[(e + E_EDGES) * 3 + 0] = -qx * inv;
        g_norm[(e + E_EDGES) * 3 + 1] = -qy * inv;
        g_norm[(e + E_EDGES) * 3 + 2] = -qz * inv;
        float td = tanhf(dis);
        #pragma unroll
        for (int k = 0; k < DISD; k++)
            sdis[h][k] = tanhf(td * W_dis[k] + b_dis[k]);
    }
    __syncthreads();

    float aa[4] = {0.f, 0.f, 0.f, 0.f};   // a_i  : slots {e0, e0+1, e0+E, e0+1+E}
    float bb[4] = {0.f, 0.f, 0.f, 0.f};   // b_j
    float mm[4] = {0.f, 0.f, 0.f, 0.f};   // link (me2 without bias)

    const float4* wrow = (const float4*)(W_att + m * WATT_LD);
    const float4* lrow = (const float4*)(W_link + m * WLNK_LD);
    const float4* pu0 = (const float4*)su[0];
    const float4* pv0 = (const float4*)sv[0];
    const float4* pu1 = (const float4*)su[1];
    const float4* pv1 = (const float4*)sv[1];

    int k0 = h * 16;
    #pragma unroll 4
    for (int k = k0; k < k0 + 16; k++) {
        float4 wva = wrow[k];        // A: hv_v  (cols 0..127)
        float4 wua = wrow[34 + k];   // A: hv_u  (cols 136..263)
        float4 wvb = wrow[66 + k];   // b: hv_v  (cols 264..391)
        float4 wum = lrow[k];        // link: hv_u
        float4 wvm = lrow[34 + k];   // link: hv_v
        float4 u0 = pu0[k], v0 = pv0[k], u1 = pu1[k], v1 = pv1[k];
        aa[0] += dot4(v0, wva) + dot4(u0, wua);
        aa[1] += dot4(v1, wva) + dot4(u1, wua);
        aa[2] += dot4(u0, wva) + dot4(v0, wua);   // reverse: swap u/v
        aa[3] += dot4(u1, wva) + dot4(v1, wua);
        bb[0] += dot4(v0, wvb);
        bb[1] += dot4(v1, wvb);
        bb[2] += dot4(u0, wvb);
        bb[3] += dot4(u1, wvb);
        mm[0] += dot4(u0, wum) + dot4(v0, wvm);
        mm[1] += dot4(u1, wum) + dot4(v1, wvm);
        mm[2] += dot4(v0, wum) + dot4(u0, wvm);
        mm[3] += dot4(v1, wum) + dot4(u1, wvm);
    }
    if (h == 0) {   // dis block (same dis for fwd and rev)
        const float4* pd0 = (const float4*)sdis[0];
        const float4* pd1 = (const float4*)sdis[1];
        #pragma unroll
        for (int kk = 0; kk < 2; kk++) {
            float4 wda = wrow[32 + kk];  // A: dis   (cols 128..135)
            float4 wdb = wrow[98 + kk];  // b: dis   (cols 392..399)
            float4 wdm = lrow[32 + kk];  // link: dis
            float4 d0 = pd0[kk], d1 = pd1[kk];
            aa[0] += dot4(d0, wda); aa[2] += dot4(d0, wda);
            aa[1] += dot4(d1, wda); aa[3] += dot4(d1, wda);
            bb[0] += dot4(d0, wdb); bb[2] += dot4(d0, wdb);
            bb[1] += dot4(d1, wdb); bb[3] += dot4(d1, wdb);
            mm[0] += dot4(d0, wdm); mm[2] += dot4(d0, wdm);
            mm[1] += dot4(d1, wdm); mm[3] += dot4(d1, wdm);
        }
    }

    // combine split-K halves
    if (h == 1) {
        #pragma unroll
        for (int j = 0; j < 4; j++) {
            spart[j][m] = aa[j];
            spart[4 + j][m] = bb[j];
            spart[8 + j][m] = mm[j];
        }
    }
    __syncthreads();
    if (h == 0) {
        #pragma unroll
        for (int j = 0; j < 4; j++) {
            aa[j] += spart[j][m];
            bb[j] += spart[4 + j][m];
            mm[j] += spart[8 + j][m];
        }
        #pragma unroll
        for (int i = 0; i < 2; i++) {
            int d = e0 + i;
            g_a[d * MV + m] = aa[i];
            g_b[d * MV + m] = bb[i];
            g_a[(d + E_EDGES) * MV + m] = aa[2 + i];
            g_b[(d + E_EDGES) * MV + m] = bb[2 + i];
            float x = mm[i] + mm[2 + i] + 2.0f * b_link[m];
            out[N_NODES * MV + d * MV + m] = (x >= 0.0f) ? x : 0.01f * x;
        }
    }
}

// ========== K3: sparse attend (max over relu'd neighbor scores) ===============
__global__ void __launch_bounds__(128) k_attend(const float* __restrict__ W_ang,
                                                const float* __restrict__ b_ang) {
    int i = blockIdx.x;
    int t = threadIdx.x;
    __shared__ float sh_t[ANGD];

    float wc[ANGD];
    #pragma unroll
    for (int k = 0; k < ANGD; k++) wc[k] = g_wc[k * MV + t];   // coalesced

    float ai = g_a[i * MV + t];
    float nix = g_norm[i * 3 + 0], niy = g_norm[i * 3 + 1], niz = g_norm[i * 3 + 2];
    int u = g_U[i];
    int cnt = g_adjU_cnt[u];

    float amax = 0.0f;   // relu floor (ee=0 rows contribute exactly 0)
    for (int idx = 0; idx < cnt; idx++) {
        int j = g_adjU[u * CAP + idx];
        if (t < ANGD) {
            float ang = nix * g_norm[j * 3 + 0] + niy * g_norm[j * 3 + 1] + niz * g_norm[j * 3 + 2];
            sh_t[t] = tanhf(ang * W_ang[t] + b_ang[t]);
        }
        __syncthreads();
        float c = 0.0f;
        #pragma unroll
        for (int k = 0; k < ANGD; k++) c += sh_t[k] * wc[k];
        amax = fmaxf(amax, ai + g_b[j * MV + t] + c);
        __syncthreads();
    }
    g_att[i * MV + t] = amax;
    atomicAdd(&g_attsum[(i & 3) * MV + t], amax);   // padded column sum
}

// ========== K4: softmax-gather + elu -> mv_ftr ================================
__global__ void __launch_bounds__(128) k_mv(float* __restrict__ out) {
    int n = blockIdx.x;
    int t = threadIdx.x;
    int cnt = g_adjV_cnt[n];
    float r;
    if (cnt == 0) {
        // all logits -1e6 -> uniform softmax over all 640 rows
        r = (g_attsum[t] + g_attsum[MV + t] + g_attsum[2 * MV + t] + g_attsum[3 * MV + t])
            * (1.0f / (float)DE);
    } else {
        float mx = -1e30f;
        for (int idx = 0; idx < cnt; idx++)
            mx = fmaxf(mx, g_align[g_adjV[n * CAP + idx]]);
        float den = 0.0f, acc = 0.0f;
        for (int idx = 0; idx < cnt; idx++) {
            int d = g_adjV[n * CAP + idx];
            float w = expf(g_align[d] - mx);
            den += w;
            acc += w * g_att[d * MV + t];
        }
        r = acc / den;
    }
    out[n * MV + t] = (r > 0.0f) ? r : expm1f(r);   // elu
}

// ---------------- launch ----------------
extern "C" void kernel_launch(void* const* d_in, const int* in_sizes, int n_in,
                              void* d_out, int out_size) {
    const float* hv      = (const float*)d_in[0];
    const float* he      = (const float*)d_in[1];
    const float* q       = (const float*)d_in[3];
    const float* vew1    = (const float*)d_in[4];
    const float* vew2    = (const float*)d_in[5];
    const float* W_dis   = (const float*)d_in[8];
    const float* b_dis   = (const float*)d_in[9];
    const float* W_ang   = (const float*)d_in[10];
    const float* b_ang   = (const float*)d_in[11];
    const float* W_att   = (const float*)d_in[12];
    const float* W_align = (const float*)d_in[13];
    const float* b_align = (const float*)d_in[14];
    const float* W_link  = (const float*)d_in[15];
    const float* b_link  = (const float*)d_in[16];
    float* out = (float*)d_out;

    k_build<<<353, 256>>>(vew1, vew2, W_att);
    k_gemm<<<E_EDGES / 2, 256>>>(hv, he, q, W_att, W_link, b_link,
                                 W_align, b_align, W_dis, b_dis, out);
    k_attend<<<DE, 128>>>(W_ang, b_ang);
    k_mv<<<N_NODES, 128>>>(out);
}